// round 15
// baseline (speedup 1.0000x reference)
#include <cuda_runtime.h>
#include <cuda_bf16.h>
#include <string.h>

#define Bb 2
#define Hh 16
#define Ss 2048
#define Dd 128
#define BM 64
#define BN 32
#define NT 128

#define SQ 136
#define SK 136

// smem layout (bf16 elements)
#define OFF_QH 0
#define OFF_QL 8704               // 64*136
#define BUF0   17408
#define BUFSZ  17408              // KH,KL,VH,VL each 32*136=4352
#define KH_O   0
#define KL_O   4352
#define VH_O   8704
#define VL_O   13056
#define SMEM_ELEMS (BUF0 + 2*BUFSZ)     // 52224
#define SMEM_BYTES (SMEM_ELEMS*2)       // 104448 -> 2 CTAs/SM

#define NELEM ((size_t)Bb*Hh*Ss*Dd)
#define TOT4  (NELEM/4)

// pre-split bf16 planes
__device__ __align__(16) __nv_bfloat16 g_kh[NELEM];
__device__ __align__(16) __nv_bfloat16 g_kl[NELEM];
__device__ __align__(16) __nv_bfloat16 g_vh[NELEM];
__device__ __align__(16) __nv_bfloat16 g_vl[NELEM];
__device__ int g_len[Bb];
__device__ int g_off;

__device__ __forceinline__ void split_pack(float x, float y, unsigned &hi, unsigned &lo) {
    __nv_bfloat162 hv = __floats2bfloat162_rn(x, y);
    float2 hf = __bfloat1622float2(hv);
    __nv_bfloat162 lv = __floats2bfloat162_rn(x - hf.x, y - hf.y);
    memcpy(&hi, &hv, 4);
    memcpy(&lo, &lv, 4);
}

// merged prep (mask lengths + offset) + K/V split-conversion: 2 launches per call
__global__ void prep_convert(const float* __restrict__ K, const float* __restrict__ V,
                             const unsigned char* __restrict__ mask, const int* offp) {
    if (blockIdx.x < Bb) {     // mask length for batch b (also converts below)
        __shared__ int cnt;
        int b = blockIdx.x;
        if (threadIdx.x == 0) cnt = 0;
        __syncthreads();
        bool w4 = (mask[1] == 0);
        int local = 0;
        for (int j = threadIdx.x; j < Ss; j += blockDim.x) {
            bool valid = w4 ? (((const unsigned int*)mask)[(size_t)b * Ss + j] != 0u)
                            : (mask[(size_t)b * Ss + j] != 0);
            local += valid ? 1 : 0;
        }
        atomicAdd(&cnt, local);
        __syncthreads();
        if (threadIdx.x == 0) {
            g_len[b] = cnt;
            if (b == 0) g_off = offp ? offp[0] : 0;
        }
    }
    size_t i = (size_t)blockIdx.x * blockDim.x + threadIdx.x;
    if (i >= TOT4) return;
    float4 k4 = ((const float4*)K)[i];
    uint2 hi, lo;
    split_pack(k4.x, k4.y, hi.x, lo.x);
    split_pack(k4.z, k4.w, hi.y, lo.y);
    ((uint2*)g_kh)[i] = hi; ((uint2*)g_kl)[i] = lo;
    float4 v4 = ((const float4*)V)[i];
    split_pack(v4.x, v4.y, hi.x, lo.x);
    split_pack(v4.z, v4.w, hi.y, lo.y);
    ((uint2*)g_vh)[i] = hi; ((uint2*)g_vl)[i] = lo;
}

#define LDSM4(r0,r1,r2,r3,addr) \
    asm volatile("ldmatrix.sync.aligned.m8n8.x4.shared.b16 {%0,%1,%2,%3}, [%4];\n" \
        : "=r"(r0),"=r"(r1),"=r"(r2),"=r"(r3) : "r"(addr))
#define LDSM4T(r0,r1,r2,r3,addr) \
    asm volatile("ldmatrix.sync.aligned.m8n8.x4.trans.shared.b16 {%0,%1,%2,%3}, [%4];\n" \
        : "=r"(r0),"=r"(r1),"=r"(r2),"=r"(r3) : "r"(addr))
#define MMA_BF16(c,a,b0,b1) \
    asm volatile("mma.sync.aligned.m16n8k16.row.col.f32.bf16.bf16.f32 " \
        "{%0,%1,%2,%3}, {%4,%5,%6,%7}, {%8,%9}, {%0,%1,%2,%3};\n" \
        : "+f"(c[0]),"+f"(c[1]),"+f"(c[2]),"+f"(c[3]) \
        : "r"(a[0]),"r"(a[1]),"r"(a[2]),"r"(a[3]),"r"(b0),"r"(b1))
#define CPA16(dst, src) \
    asm volatile("cp.async.cg.shared.global [%0], [%1], 16;" :: "r"(dst), "l"(src) : "memory")
#define CPA_COMMIT() asm volatile("cp.async.commit_group;" ::: "memory")
#define CPA_WAIT0()  asm volatile("cp.async.wait_group 0;" ::: "memory")

// stage one 32-row K/V tile (4 planes) via cp.async; 128 threads
__device__ __forceinline__ void stage_tile(unsigned sb, unsigned bufE, size_t gbase,
                                           int tid) {
    const int c = tid & 15;
    const int r0 = tid >> 4;
    const unsigned dstb = sb + bufE * 2 + (unsigned)c * 16;
    const size_t srcb = gbase + (size_t)c * 8;
    #pragma unroll
    for (int j = 0; j < 4; j++) {
        const int r = r0 + 8 * j;
        const unsigned drow = (unsigned)r * (SK * 2);
        const size_t srow = srcb + (size_t)r * Dd;
        CPA16(dstb + KH_O * 2 + drow, g_kh + srow);
        CPA16(dstb + KL_O * 2 + drow, g_kl + srow);
        CPA16(dstb + VH_O * 2 + drow, g_vh + srow);
        CPA16(dstb + VL_O * 2 + drow, g_vl + srow);
    }
}

__global__ __launch_bounds__(NT, 2)
void attend_kernel(const float* __restrict__ Q, const float* __restrict__ Bias,
                   float* __restrict__ Out) {
    extern __shared__ unsigned short sm16[];

    const int tid = threadIdx.x;
    const int lane = tid & 31, w = tid >> 5;
    const int g = lane >> 2, t4 = lane & 3;
    const int lm = lane & 7, sel = lane >> 3;
    const int m0 = w * 16;

    const int bh = blockIdx.y;
    const int b = bh / Hh;
    const int h = bh - b * Hh;
    const int q0 = (gridDim.x - 1 - blockIdx.x) * BM;  // heavy CTAs first

    const int L = g_len[b];
    const int off = g_off;

    const float* qb = Q + ((size_t)bh * Ss + q0) * Dd;
    const float* bb = Bias + (size_t)h * Ss * Ss;
    float* ob = Out + ((size_t)bh * Ss + q0) * Dd;
    const size_t kvbase = (size_t)bh * Ss * Dd;

    // ---- stage Q (64 x 128) as bf16 hi/lo ----
    #pragma unroll 4
    for (int t = tid; t < BM * (Dd / 4); t += NT) {
        int r = t >> 5, c4 = t & 31;
        float4 v = ((const float4*)(qb + (size_t)r * Dd))[c4];
        unsigned h0, l0, h1, l1;
        split_pack(v.x, v.y, h0, l0);
        split_pack(v.z, v.w, h1, l1);
        int base = r * SQ + c4 * 4;
        *(unsigned*)&sm16[OFF_QH + base]     = h0;
        *(unsigned*)&sm16[OFF_QH + base + 2] = h1;
        *(unsigned*)&sm16[OFF_QL + base]     = l0;
        *(unsigned*)&sm16[OFF_QL + base + 2] = l1;
    }

    // fragment lane addressing
    const unsigned smemB = (unsigned)__cvta_generic_to_shared(sm16);
    const int rowA  = m0 + lm + (sel & 1) * 8;
    const int rowBK = lm + ((sel & 2) >> 1) * 8;
    const int rowBV = lm + (sel & 1) * 8;
    const unsigned selA16 = ((sel & 2) >> 1) * 16;
    const unsigned selB16 = (sel & 1) * 16;

    const unsigned aQH = smemB + (OFF_QH + rowA * SQ) * 2 + selA16;
    const unsigned aQL = smemB + (OFF_QL + rowA * SQ) * 2 + selA16;
    const unsigned laneKH = (unsigned)(KH_O + rowBK * SK) * 2 + selB16;
    const unsigned laneKL = (unsigned)(KL_O + rowBK * SK) * 2 + selB16;
    const unsigned laneVH = (unsigned)(VH_O + rowBV * SK) * 2 + selA16;
    const unsigned laneVL = (unsigned)(VL_O + rowBV * SK) * 2 + selA16;

    float o[16][4];
    #pragma unroll
    for (int nf = 0; nf < 16; nf++)
        #pragma unroll
        for (int c = 0; c < 4; c++) o[nf][c] = 0.f;
    float mrow0 = -1e30f, mrow1 = -1e30f;
    float lp0 = 0.f, lp1 = 0.f;          // per-lane partial sums (deferred reduce)

    const int i0 = q0 + m0 + g;
    const int i1 = i0 + 8;

    int maxj = q0 + BM - 1 - off;
    if (maxj > L - 1) maxj = L - 1;
    const int ntiles = (maxj >= 0) ? (maxj / BN + 1) : 0;

    const float scale = 0.08838834764831845f;  // 128^-0.5

    // bias register double buffer
    float2 bC[8], bN[8];
    // cached Q-hi fragments (invariant across tiles)
    unsigned qh[8][4];

    if (ntiles > 0) {
        stage_tile(smemB, BUF0, kvbase, tid);
        CPA_COMMIT();
        #pragma unroll
        for (int nf = 0; nf < 4; nf++) {
            const int j0 = nf * 8 + 2 * t4;
            bC[2 * nf]     = __ldg((const float2*)(bb + (size_t)i0 * Ss + j0));
            bC[2 * nf + 1] = __ldg((const float2*)(bb + (size_t)i1 * Ss + j0));
        }
    }
    __syncthreads();           // Q staged -> cache Qh fragments once
    #pragma unroll
    for (int kk = 0; kk < 8; kk++)
        LDSM4(qh[kk][0], qh[kk][1], qh[kk][2], qh[kk][3], aQH + kk * 32);

    for (int t = 0; t < ntiles; ++t) {
        const int n0 = t * BN;
        const bool have_next = (t + 1 < ntiles);
        CPA_WAIT0();
        __syncthreads();

        if (have_next) {
            stage_tile(smemB, BUF0 + (unsigned)((t + 1) & 1) * BUFSZ,
                       kvbase + (size_t)(n0 + BN) * Dd, tid);
            CPA_COMMIT();
            const int nn0 = n0 + BN;
            #pragma unroll
            for (int nf = 0; nf < 4; nf++) {
                const int j0 = nn0 + nf * 8 + 2 * t4;
                bN[2 * nf]     = __ldg((const float2*)(bb + (size_t)i0 * Ss + j0));
                bN[2 * nf + 1] = __ldg((const float2*)(bb + (size_t)i1 * Ss + j0));
            }
        }

        const unsigned bufB = smemB + (BUF0 + (unsigned)(t & 1) * BUFSZ) * 2;
        const unsigned bKH = bufB + laneKH;
        const unsigned bKL = bufB + laneKL;
        const unsigned bVH = bufB + laneVH;
        const unsigned bVL = bufB + laneVL;

        // ---- S = Q @ K^T : 3 passes of independent MMAs per k-step ----
        float acc[4][4];
        #pragma unroll
        for (int nf = 0; nf < 4; nf++)
            #pragma unroll
            for (int c = 0; c < 4; c++) acc[nf][c] = 0.f;

        #pragma unroll
        for (int kk = 0; kk < 8; kk++) {
            unsigned al[4], kh4[2][4], kl4[2][4];
            LDSM4(al[0], al[1], al[2], al[3], aQL + kk * 32);
            #pragma unroll
            for (int nf2 = 0; nf2 < 2; nf2++) {
                const unsigned boff = nf2 * (16 * SK * 2) + kk * 32;
                LDSM4(kh4[nf2][0], kh4[nf2][1], kh4[nf2][2], kh4[nf2][3], bKH + boff);
                LDSM4(kl4[nf2][0], kl4[nf2][1], kl4[nf2][2], kl4[nf2][3], bKL + boff);
            }
            #pragma unroll
            for (int nf2 = 0; nf2 < 2; nf2++) {
                MMA_BF16(acc[2 * nf2],     qh[kk], kh4[nf2][0], kh4[nf2][1]);
                MMA_BF16(acc[2 * nf2 + 1], qh[kk], kh4[nf2][2], kh4[nf2][3]);
            }
            #pragma unroll
            for (int nf2 = 0; nf2 < 2; nf2++) {
                MMA_BF16(acc[2 * nf2],     qh[kk], kl4[nf2][0], kl4[nf2][1]);
                MMA_BF16(acc[2 * nf2 + 1], qh[kk], kl4[nf2][2], kl4[nf2][3]);
            }
            #pragma unroll
            for (int nf2 = 0; nf2 < 2; nf2++) {
                MMA_BF16(acc[2 * nf2],     al, kh4[nf2][0], kh4[nf2][1]);
                MMA_BF16(acc[2 * nf2 + 1], al, kh4[nf2][2], kh4[nf2][3]);
            }
        }

        // ---- scale + bias (prefetched) + mask ----
        const bool full = (n0 + BN - 1 <= q0 - off) && (n0 + BN <= L);
        #pragma unroll
        for (int nf = 0; nf < 4; nf++) {
            const int j0 = n0 + nf * 8 + 2 * t4;
            const float2 bi0 = bC[2 * nf];
            const float2 bi1 = bC[2 * nf + 1];
            if (full) {
                acc[nf][0] = acc[nf][0] * scale + bi0.x;
                acc[nf][1] = acc[nf][1] * scale + bi0.y;
                acc[nf][2] = acc[nf][2] * scale + bi1.x;
                acc[nf][3] = acc[nf][3] * scale + bi1.y;
            } else {
                acc[nf][0] = (j0     <= i0 - off && j0     < L) ? acc[nf][0] * scale + bi0.x : -1e30f;
                acc[nf][1] = (j0 + 1 <= i0 - off && j0 + 1 < L) ? acc[nf][1] * scale + bi0.y : -1e30f;
                acc[nf][2] = (j0     <= i1 - off && j0     < L) ? acc[nf][2] * scale + bi1.x : -1e30f;
                acc[nf][3] = (j0 + 1 <= i1 - off && j0 + 1 < L) ? acc[nf][3] * scale + bi1.y : -1e30f;
            }
        }

        // ---- online softmax; P packed into A-fragment registers ----
        float mx0 = acc[0][0], mx1 = acc[0][2];
        #pragma unroll
        for (int nf = 0; nf < 4; nf++) {
            mx0 = fmaxf(mx0, fmaxf(acc[nf][0], acc[nf][1]));
            mx1 = fmaxf(mx1, fmaxf(acc[nf][2], acc[nf][3]));
        }
        mx0 = fmaxf(mx0, __shfl_xor_sync(0xFFFFFFFFu, mx0, 1));
        mx0 = fmaxf(mx0, __shfl_xor_sync(0xFFFFFFFFu, mx0, 2));
        mx1 = fmaxf(mx1, __shfl_xor_sync(0xFFFFFFFFu, mx1, 1));
        mx1 = fmaxf(mx1, __shfl_xor_sync(0xFFFFFFFFu, mx1, 2));
        const float mn0 = fmaxf(mrow0, mx0);
        const float mn1 = fmaxf(mrow1, mx1);
        const float alpha0 = __expf(mrow0 - mn0);
        const float alpha1 = __expf(mrow1 - mn1);
        float sum0 = 0.f, sum1 = 0.f;

        unsigned ph01[4], pl01[4], ph23[4], pl23[4];
        #pragma unroll
        for (int nf = 0; nf < 4; nf++) {
            float p00 = __expf(acc[nf][0] - mn0);
            float p01 = __expf(acc[nf][1] - mn0);
            float p10 = __expf(acc[nf][2] - mn1);
            float p11 = __expf(acc[nf][3] - mn1);
            sum0 += p00 + p01;
            sum1 += p10 + p11;
            split_pack(p00, p01, ph01[nf], pl01[nf]);
            split_pack(p10, p11, ph23[nf], pl23[nf]);
        }
        // deferred: per-lane partials only; cross-lane reduce in epilogue
        lp0 = lp0 * alpha0 + sum0;
        lp1 = lp1 * alpha1 + sum1;
        mrow0 = mn0; mrow1 = mn1;

        if (alpha0 != 1.0f || alpha1 != 1.0f) {
            #pragma unroll
            for (int nf = 0; nf < 16; nf++) {
                o[nf][0] *= alpha0; o[nf][1] *= alpha0;
                o[nf][2] *= alpha1; o[nf][3] *= alpha1;
            }
        }

        // ---- O += P @ V ----
        #pragma unroll
        for (int kk = 0; kk < 2; kk++) {
            unsigned ah[4], al[4];
            ah[0] = ph01[2 * kk];     al[0] = pl01[2 * kk];
            ah[1] = ph23[2 * kk];     al[1] = pl23[2 * kk];
            ah[2] = ph01[2 * kk + 1]; al[2] = pl01[2 * kk + 1];
            ah[3] = ph23[2 * kk + 1]; al[3] = pl23[2 * kk + 1];
            #pragma unroll
            for (int half = 0; half < 2; half++) {
                unsigned bh4[4][4], bl4[4][4];
                #pragma unroll
                for (int qd = 0; qd < 4; qd++) {
                    const int nf2 = half * 4 + qd;
                    const unsigned boff = kk * (16 * SK * 2) + nf2 * 32;
                    LDSM4T(bh4[qd][0], bh4[qd][1], bh4[qd][2], bh4[qd][3], bVH + boff);
                    LDSM4T(bl4[qd][0], bl4[qd][1], bl4[qd][2], bl4[qd][3], bVL + boff);
                }
                #pragma unroll
                for (int qd = 0; qd < 4; qd++) {
                    const int nf2 = half * 4 + qd;
                    MMA_BF16(o[2 * nf2],     ah, bh4[qd][0], bh4[qd][1]);
                    MMA_BF16(o[2 * nf2 + 1], ah, bh4[qd][2], bh4[qd][3]);
                }
                #pragma unroll
                for (int qd = 0; qd < 4; qd++) {
                    const int nf2 = half * 4 + qd;
                    MMA_BF16(o[2 * nf2],     ah, bl4[qd][0], bl4[qd][1]);
                    MMA_BF16(o[2 * nf2 + 1], ah, bl4[qd][2], bl4[qd][3]);
                }
                #pragma unroll
                for (int qd = 0; qd < 4; qd++) {
                    const int nf2 = half * 4 + qd;
                    MMA_BF16(o[2 * nf2],     al, bh4[qd][0], bh4[qd][1]);
                    MMA_BF16(o[2 * nf2 + 1], al, bh4[qd][2], bh4[qd][3]);
                }
            }
        }

        // rotate bias buffer
        if (have_next) {
            #pragma unroll
            for (int i = 0; i < 8; i++) bC[i] = bN[i];
        }
    }

    // ---- epilogue: final cross-lane sum reduce, normalize + write ----
    lp0 += __shfl_xor_sync(0xFFFFFFFFu, lp0, 1);
    lp0 += __shfl_xor_sync(0xFFFFFFFFu, lp0, 2);
    lp1 += __shfl_xor_sync(0xFFFFFFFFu, lp1, 1);
    lp1 += __shfl_xor_sync(0xFFFFFFFFu, lp1, 2);
    const float inv0 = (lp0 > 0.f) ? (1.f / lp0) : 0.f;
    const float inv1 = (lp1 > 0.f) ? (1.f / lp1) : 0.f;
    float* o0 = ob + (size_t)(m0 + g) * Dd + 2 * t4;
    float* o1 = ob + (size_t)(m0 + g + 8) * Dd + 2 * t4;
    #pragma unroll
    for (int nf = 0; nf < 16; nf++) {
        float2 w0 = make_float2(o[nf][0] * inv0, o[nf][1] * inv0);
        float2 w1 = make_float2(o[nf][2] * inv1, o[nf][3] * inv1);
        *(float2*)&o0[nf * 8] = w0;
        *(float2*)&o1[nf * 8] = w1;
    }
}

extern "C" void kernel_launch(void* const* d_in, const int* in_sizes, int n_in,
                              void* d_out, int out_size) {
    const float* q = (const float*)d_in[0];
    const float* k = (const float*)d_in[1];
    const float* v = (const float*)d_in[2];
    const unsigned char* mask = (const unsigned char*)d_in[3];
    const float* bias = (const float*)d_in[4];
    const int* off = (n_in > 5) ? (const int*)d_in[5] : nullptr;
    float* out = (float*)d_out;

    cudaFuncSetAttribute(attend_kernel,
                         cudaFuncAttributeMaxDynamicSharedMemorySize, SMEM_BYTES);

    prep_convert<<<(int)(TOT4 / 256), 256>>>(k, v, mask, off);
    dim3 grid(Ss / BM, Bb * Hh);
    attend_kernel<<<grid, NT, SMEM_BYTES>>>(q, bias, out);
}

// round 16
// speedup vs baseline: 1.6169x; 1.6169x over previous
#include <cuda_runtime.h>
#include <cuda_fp16.h>
#include <string.h>

#define Bb 2
#define Hh 16
#define Ss 2048
#define Dd 128
#define BM 64
#define BN 32
#define NT 128

#define SQ 136
#define SK 136

// smem layout (fp16 elements)
#define OFF_QH 0
#define OFF_QL 8704               // 64*136
#define BUF0   17408
#define BUFSZ  17408              // KH,KL,VH,VL each 32*136=4352
#define KH_O   0
#define KL_O   4352
#define VH_O   8704
#define VL_O   13056
#define SMEM_ELEMS (BUF0 + 2*BUFSZ)     // 52224
#define SMEM_BYTES (SMEM_ELEMS*2)       // 104448 -> 2 CTAs/SM

#define NELEM ((size_t)Bb*Hh*Ss*Dd)
#define TOT4  (NELEM/4)

// pre-split fp16 planes
__device__ __align__(16) __half g_kh[NELEM];
__device__ __align__(16) __half g_kl[NELEM];
__device__ __align__(16) __half g_vh[NELEM];
__device__ __align__(16) __half g_vl[NELEM];
__device__ int g_len[Bb];
__device__ int g_off;

__global__ void prep_kernel(const unsigned char* __restrict__ mask, const int* offp) {
    int b = blockIdx.x;
    __shared__ int cnt;
    if (threadIdx.x == 0) cnt = 0;
    __syncthreads();
    bool w4 = (mask[1] == 0);
    int local = 0;
    for (int j = threadIdx.x; j < Ss; j += blockDim.x) {
        bool valid = w4 ? (((const unsigned int*)mask)[(size_t)b * Ss + j] != 0u)
                        : (mask[(size_t)b * Ss + j] != 0);
        local += valid ? 1 : 0;
    }
    atomicAdd(&cnt, local);
    __syncthreads();
    if (threadIdx.x == 0) {
        g_len[b] = cnt;
        if (b == 0) g_off = offp ? offp[0] : 0;
    }
}

__device__ __forceinline__ void split_pack(float x, float y, unsigned &hi, unsigned &lo) {
    __half2 hv = __floats2half2_rn(x, y);
    float2 hf = __half22float2(hv);
    __half2 lv = __floats2half2_rn(x - hf.x, y - hf.y);
    memcpy(&hi, &hv, 4);
    memcpy(&lo, &lv, 4);
}

__device__ __forceinline__ unsigned pack_h2(float x, float y) {
    __half2 hv = __floats2half2_rn(x, y);
    unsigned r; memcpy(&r, &hv, 4);
    return r;
}

__global__ void convert_kv(const float* __restrict__ K, const float* __restrict__ V) {
    size_t i = (size_t)blockIdx.x * blockDim.x + threadIdx.x;
    if (i >= TOT4) return;
    float4 k4 = ((const float4*)K)[i];
    uint2 hi, lo;
    split_pack(k4.x, k4.y, hi.x, lo.x);
    split_pack(k4.z, k4.w, hi.y, lo.y);
    ((uint2*)g_kh)[i] = hi; ((uint2*)g_kl)[i] = lo;
    float4 v4 = ((const float4*)V)[i];
    split_pack(v4.x, v4.y, hi.x, lo.x);
    split_pack(v4.z, v4.w, hi.y, lo.y);
    ((uint2*)g_vh)[i] = hi; ((uint2*)g_vl)[i] = lo;
}

#define LDSM4(r0,r1,r2,r3,addr) \
    asm volatile("ldmatrix.sync.aligned.m8n8.x4.shared.b16 {%0,%1,%2,%3}, [%4];\n" \
        : "=r"(r0),"=r"(r1),"=r"(r2),"=r"(r3) : "r"(addr))
#define LDSM4T(r0,r1,r2,r3,addr) \
    asm volatile("ldmatrix.sync.aligned.m8n8.x4.trans.shared.b16 {%0,%1,%2,%3}, [%4];\n" \
        : "=r"(r0),"=r"(r1),"=r"(r2),"=r"(r3) : "r"(addr))
#define MMA_F16(c,a,b0,b1) \
    asm volatile("mma.sync.aligned.m16n8k16.row.col.f32.f16.f16.f32 " \
        "{%0,%1,%2,%3}, {%4,%5,%6,%7}, {%8,%9}, {%0,%1,%2,%3};\n" \
        : "+f"(c[0]),"+f"(c[1]),"+f"(c[2]),"+f"(c[3]) \
        : "r"(a[0]),"r"(a[1]),"r"(a[2]),"r"(a[3]),"r"(b0),"r"(b1))
#define CPA16(dst, src) \
    asm volatile("cp.async.cg.shared.global [%0], [%1], 16;" :: "r"(dst), "l"(src) : "memory")
#define CPA_COMMIT() asm volatile("cp.async.commit_group;" ::: "memory")
#define CPA_WAIT0()  asm volatile("cp.async.wait_group 0;" ::: "memory")

// stage one 32-row K/V tile (4 planes) via cp.async; 128 threads
__device__ __forceinline__ void stage_tile(unsigned sb, unsigned bufE, size_t gbase,
                                           int tid) {
    const int c = tid & 15;
    const int r0 = tid >> 4;
    const unsigned dstb = sb + bufE * 2 + (unsigned)c * 16;
    const size_t srcb = gbase + (size_t)c * 8;
    #pragma unroll
    for (int j = 0; j < 4; j++) {
        const int r = r0 + 8 * j;
        const unsigned drow = (unsigned)r * (SK * 2);
        const size_t srow = srcb + (size_t)r * Dd;
        CPA16(dstb + KH_O * 2 + drow, g_kh + srow);
        CPA16(dstb + KL_O * 2 + drow, g_kl + srow);
        CPA16(dstb + VH_O * 2 + drow, g_vh + srow);
        CPA16(dstb + VL_O * 2 + drow, g_vl + srow);
    }
}

__global__ __launch_bounds__(NT, 2)
void attend_kernel(const float* __restrict__ Q, const float* __restrict__ Bias,
                   float* __restrict__ Out) {
    extern __shared__ unsigned short sm16[];

    const int tid = threadIdx.x;
    const int lane = tid & 31, w = tid >> 5;
    const int g = lane >> 2, t4 = lane & 3;
    const int lm = lane & 7, sel = lane >> 3;
    const int m0 = w * 16;

    const int bh = blockIdx.y;
    const int b = bh / Hh;
    const int h = bh - b * Hh;
    const int q0 = (gridDim.x - 1 - blockIdx.x) * BM;  // heavy CTAs first

    const int L = g_len[b];
    const int off = g_off;

    const float* qb = Q + ((size_t)bh * Ss + q0) * Dd;
    const float* bb = Bias + (size_t)h * Ss * Ss;
    float* ob = Out + ((size_t)bh * Ss + q0) * Dd;
    const size_t kvbase = (size_t)bh * Ss * Dd;

    // ---- stage Q (64 x 128) as fp16 hi/lo ----
    #pragma unroll 4
    for (int t = tid; t < BM * (Dd / 4); t += NT) {
        int r = t >> 5, c4 = t & 31;
        float4 v = ((const float4*)(qb + (size_t)r * Dd))[c4];
        unsigned h0, l0, h1, l1;
        split_pack(v.x, v.y, h0, l0);
        split_pack(v.z, v.w, h1, l1);
        int base = r * SQ + c4 * 4;
        *(unsigned*)&sm16[OFF_QH + base]     = h0;
        *(unsigned*)&sm16[OFF_QH + base + 2] = h1;
        *(unsigned*)&sm16[OFF_QL + base]     = l0;
        *(unsigned*)&sm16[OFF_QL + base + 2] = l1;
    }

    // fragment lane addressing
    const unsigned smemB = (unsigned)__cvta_generic_to_shared(sm16);
    const int rowA  = m0 + lm + (sel & 1) * 8;
    const int rowBK = lm + ((sel & 2) >> 1) * 8;
    const int rowBV = lm + (sel & 1) * 8;
    const unsigned selA16 = ((sel & 2) >> 1) * 16;
    const unsigned selB16 = (sel & 1) * 16;

    const unsigned aQH = smemB + (OFF_QH + rowA * SQ) * 2 + selA16;
    const unsigned aQL = smemB + (OFF_QL + rowA * SQ) * 2 + selA16;
    const unsigned laneKH = (unsigned)(KH_O + rowBK * SK) * 2 + selB16;
    const unsigned laneKL = (unsigned)(KL_O + rowBK * SK) * 2 + selB16;
    const unsigned laneVH = (unsigned)(VH_O + rowBV * SK) * 2 + selA16;
    const unsigned laneVL = (unsigned)(VL_O + rowBV * SK) * 2 + selA16;

    float o[16][4];
    #pragma unroll
    for (int nf = 0; nf < 16; nf++)
        #pragma unroll
        for (int c = 0; c < 4; c++) o[nf][c] = 0.f;
    float mrow0 = -1e30f, mrow1 = -1e30f, lrow0 = 0.f, lrow1 = 0.f;

    const int i0 = q0 + m0 + g;
    const int i1 = i0 + 8;

    int maxj = q0 + BM - 1 - off;
    if (maxj > L - 1) maxj = L - 1;
    const int ntiles = (maxj >= 0) ? (maxj / BN + 1) : 0;

    const float scale = 0.08838834764831845f;  // 128^-0.5

    // bias register double buffer: bC = tile t, bN = tile t+1
    float2 bC[8], bN[8];

    if (ntiles > 0) {
        stage_tile(smemB, BUF0, kvbase, tid);
        CPA_COMMIT();
        #pragma unroll
        for (int nf = 0; nf < 4; nf++) {
            const int j0 = nf * 8 + 2 * t4;
            bC[2 * nf]     = __ldg((const float2*)(bb + (size_t)i0 * Ss + j0));
            bC[2 * nf + 1] = __ldg((const float2*)(bb + (size_t)i1 * Ss + j0));
        }
    }

    for (int t = 0; t < ntiles; ++t) {
        const int n0 = t * BN;
        const bool have_next = (t + 1 < ntiles);
        CPA_WAIT0();
        __syncthreads();

        if (have_next) {
            stage_tile(smemB, BUF0 + (unsigned)((t + 1) & 1) * BUFSZ,
                       kvbase + (size_t)(n0 + BN) * Dd, tid);
            CPA_COMMIT();
            const int nn0 = n0 + BN;
            #pragma unroll
            for (int nf = 0; nf < 4; nf++) {
                const int j0 = nn0 + nf * 8 + 2 * t4;
                bN[2 * nf]     = __ldg((const float2*)(bb + (size_t)i0 * Ss + j0));
                bN[2 * nf + 1] = __ldg((const float2*)(bb + (size_t)i1 * Ss + j0));
            }
        }

        const unsigned bufB = smemB + (BUF0 + (unsigned)(t & 1) * BUFSZ) * 2;
        const unsigned bKH = bufB + laneKH;
        const unsigned bKL = bufB + laneKL;
        const unsigned bVH = bufB + laneVH;
        const unsigned bVL = bufB + laneVL;

        // ---- S = Q @ K^T (fp16 3-term: Qh*Kh + Qh*Kl + Ql*Kh) ----
        float acc[4][4];
        #pragma unroll
        for (int nf = 0; nf < 4; nf++)
            #pragma unroll
            for (int c = 0; c < 4; c++) acc[nf][c] = 0.f;

        #pragma unroll
        for (int kk = 0; kk < 8; kk++) {
            unsigned ah[4], al[4], kh4[2][4], kl4[2][4];
            LDSM4(ah[0], ah[1], ah[2], ah[3], aQH + kk * 32);
            LDSM4(al[0], al[1], al[2], al[3], aQL + kk * 32);
            #pragma unroll
            for (int nf2 = 0; nf2 < 2; nf2++) {
                const unsigned boff = nf2 * (16 * SK * 2) + kk * 32;
                LDSM4(kh4[nf2][0], kh4[nf2][1], kh4[nf2][2], kh4[nf2][3], bKH + boff);
                LDSM4(kl4[nf2][0], kl4[nf2][1], kl4[nf2][2], kl4[nf2][3], bKL + boff);
            }
            #pragma unroll
            for (int nf2 = 0; nf2 < 2; nf2++) {
                MMA_F16(acc[2 * nf2],     ah, kh4[nf2][0], kh4[nf2][1]);
                MMA_F16(acc[2 * nf2 + 1], ah, kh4[nf2][2], kh4[nf2][3]);
            }
            #pragma unroll
            for (int nf2 = 0; nf2 < 2; nf2++) {
                MMA_F16(acc[2 * nf2],     ah, kl4[nf2][0], kl4[nf2][1]);
                MMA_F16(acc[2 * nf2 + 1], ah, kl4[nf2][2], kl4[nf2][3]);
            }
            #pragma unroll
            for (int nf2 = 0; nf2 < 2; nf2++) {
                MMA_F16(acc[2 * nf2],     al, kh4[nf2][0], kh4[nf2][1]);
                MMA_F16(acc[2 * nf2 + 1], al, kh4[nf2][2], kh4[nf2][3]);
            }
        }

        // ---- scale + bias (prefetched) + mask ----
        const bool full = (n0 + BN - 1 <= q0 - off) && (n0 + BN <= L);
        #pragma unroll
        for (int nf = 0; nf < 4; nf++) {
            const int j0 = n0 + nf * 8 + 2 * t4;
            const float2 bi0 = bC[2 * nf];
            const float2 bi1 = bC[2 * nf + 1];
            if (full) {
                acc[nf][0] = acc[nf][0] * scale + bi0.x;
                acc[nf][1] = acc[nf][1] * scale + bi0.y;
                acc[nf][2] = acc[nf][2] * scale + bi1.x;
                acc[nf][3] = acc[nf][3] * scale + bi1.y;
            } else {
                acc[nf][0] = (j0     <= i0 - off && j0     < L) ? acc[nf][0] * scale + bi0.x : -1e30f;
                acc[nf][1] = (j0 + 1 <= i0 - off && j0 + 1 < L) ? acc[nf][1] * scale + bi0.y : -1e30f;
                acc[nf][2] = (j0     <= i1 - off && j0     < L) ? acc[nf][2] * scale + bi1.x : -1e30f;
                acc[nf][3] = (j0 + 1 <= i1 - off && j0 + 1 < L) ? acc[nf][3] * scale + bi1.y : -1e30f;
            }
        }

        // ---- online softmax; P packed (single fp16) into A-fragment registers ----
        float mx0 = acc[0][0], mx1 = acc[0][2];
        #pragma unroll
        for (int nf = 0; nf < 4; nf++) {
            mx0 = fmaxf(mx0, fmaxf(acc[nf][0], acc[nf][1]));
            mx1 = fmaxf(mx1, fmaxf(acc[nf][2], acc[nf][3]));
        }
        mx0 = fmaxf(mx0, __shfl_xor_sync(0xFFFFFFFFu, mx0, 1));
        mx0 = fmaxf(mx0, __shfl_xor_sync(0xFFFFFFFFu, mx0, 2));
        mx1 = fmaxf(mx1, __shfl_xor_sync(0xFFFFFFFFu, mx1, 1));
        mx1 = fmaxf(mx1, __shfl_xor_sync(0xFFFFFFFFu, mx1, 2));
        const float mn0 = fmaxf(mrow0, mx0);
        const float mn1 = fmaxf(mrow1, mx1);
        const float alpha0 = __expf(mrow0 - mn0);
        const float alpha1 = __expf(mrow1 - mn1);
        float sum0 = 0.f, sum1 = 0.f;

        unsigned ph01[4], ph23[4];
        #pragma unroll
        for (int nf = 0; nf < 4; nf++) {
            float p00 = __expf(acc[nf][0] - mn0);
            float p01 = __expf(acc[nf][1] - mn0);
            float p10 = __expf(acc[nf][2] - mn1);
            float p11 = __expf(acc[nf][3] - mn1);
            sum0 += p00 + p01;
            sum1 += p10 + p11;
            ph01[nf] = pack_h2(p00, p01);
            ph23[nf] = pack_h2(p10, p11);
        }
        sum0 += __shfl_xor_sync(0xFFFFFFFFu, sum0, 1);
        sum0 += __shfl_xor_sync(0xFFFFFFFFu, sum0, 2);
        sum1 += __shfl_xor_sync(0xFFFFFFFFu, sum1, 1);
        sum1 += __shfl_xor_sync(0xFFFFFFFFu, sum1, 2);
        lrow0 = lrow0 * alpha0 + sum0;
        lrow1 = lrow1 * alpha1 + sum1;
        mrow0 = mn0; mrow1 = mn1;

        if (alpha0 != 1.0f || alpha1 != 1.0f) {
            #pragma unroll
            for (int nf = 0; nf < 16; nf++) {
                o[nf][0] *= alpha0; o[nf][1] *= alpha0;
                o[nf][2] *= alpha1; o[nf][3] *= alpha1;
            }
        }

        // ---- O += P @ V (fp16 2-term: Ph*Vh + Ph*Vl) ----
        #pragma unroll
        for (int kk = 0; kk < 2; kk++) {
            unsigned ah[4];
            ah[0] = ph01[2 * kk];
            ah[1] = ph23[2 * kk];
            ah[2] = ph01[2 * kk + 1];
            ah[3] = ph23[2 * kk + 1];
            #pragma unroll
            for (int vh = 0; vh < 2; vh++) {
                unsigned bh4[4][4], bl4[4][4];
                #pragma unroll
                for (int qd = 0; qd < 4; qd++) {
                    const int nf2 = vh * 4 + qd;
                    const unsigned boff = kk * (16 * SK * 2) + nf2 * 32;
                    LDSM4T(bh4[qd][0], bh4[qd][1], bh4[qd][2], bh4[qd][3], bVH + boff);
                    LDSM4T(bl4[qd][0], bl4[qd][1], bl4[qd][2], bl4[qd][3], bVL + boff);
                }
                #pragma unroll
                for (int qd = 0; qd < 4; qd++) {
                    const int nf2 = vh * 4 + qd;
                    MMA_F16(o[2 * nf2],     ah, bh4[qd][0], bh4[qd][1]);
                    MMA_F16(o[2 * nf2 + 1], ah, bh4[qd][2], bh4[qd][3]);
                }
                #pragma unroll
                for (int qd = 0; qd < 4; qd++) {
                    const int nf2 = vh * 4 + qd;
                    MMA_F16(o[2 * nf2],     ah, bl4[qd][0], bl4[qd][1]);
                    MMA_F16(o[2 * nf2 + 1], ah, bl4[qd][2], bl4[qd][3]);
                }
            }
        }

        // rotate bias buffer
        if (have_next) {
            #pragma unroll
            for (int i = 0; i < 8; i++) bC[i] = bN[i];
        }
    }

    // ---- normalize + write ----
    const float inv0 = (lrow0 > 0.f) ? (1.f / lrow0) : 0.f;
    const float inv1 = (lrow1 > 0.f) ? (1.f / lrow1) : 0.f;
    float* o0 = ob + (size_t)(m0 + g) * Dd + 2 * t4;
    float* o1 = ob + (size_t)(m0 + g + 8) * Dd + 2 * t4;
    #pragma unroll
    for (int nf = 0; nf < 16; nf++) {
        float2 w0 = make_float2(o[nf][0] * inv0, o[nf][1] * inv0);
        float2 w1 = make_float2(o[nf][2] * inv1, o[nf][3] * inv1);
        *(float2*)&o0[nf * 8] = w0;
        *(float2*)&o1[nf * 8] = w1;
    }
}

extern "C" void kernel_launch(void* const* d_in, const int* in_sizes, int n_in,
                              void* d_out, int out_size) {
    const float* q = (const float*)d_in[0];
    const float* k = (const float*)d_in[1];
    const float* v = (const float*)d_in[2];
    const unsigned char* mask = (const unsigned char*)d_in[3];
    const float* bias = (const float*)d_in[4];
    const int* off = (n_in > 5) ? (const int*)d_in[5] : nullptr;
    float* out = (float*)d_out;

    cudaFuncSetAttribute(attend_kernel,
                         cudaFuncAttributeMaxDynamicSharedMemorySize, SMEM_BYTES);

    prep_kernel<<<Bb, 256>>>(mask, off);
    convert_kv<<<(int)(TOT4 / 256), 256>>>(k, v);
    dim3 grid(Ss / BM, Bb * Hh);
    attend_kernel<<<grid, NT, SMEM_BYTES>>>(q, bias, out);
}

// round 17
// speedup vs baseline: 1.7325x; 1.0715x over previous
#include <cuda_runtime.h>
#include <cuda_fp16.h>
#include <string.h>

#define Bb 2
#define Hh 16
#define Ss 2048
#define Dd 128
#define BM 64
#define BN 32
#define NT 128

#define SQ 136
#define SK 136

// smem layout (fp16 elements) — Q-lo plane eliminated
#define OFF_QH 0
#define BUF0   8704               // 64*136
#define BUFSZ  17408              // KH,KL,VH,VL each 32*136=4352
#define KH_O   0
#define KL_O   4352
#define VH_O   8704
#define VL_O   13056
#define SMEM_ELEMS (BUF0 + 2*BUFSZ)     // 43520
#define SMEM_BYTES (SMEM_ELEMS*2)       // 87040 -> 2 CTAs/SM

#define NELEM ((size_t)Bb*Hh*Ss*Dd)
#define TOT4  (NELEM/4)

// pre-split fp16 planes
__device__ __align__(16) __half g_kh[NELEM];
__device__ __align__(16) __half g_kl[NELEM];
__device__ __align__(16) __half g_vh[NELEM];
__device__ __align__(16) __half g_vl[NELEM];
__device__ int g_len[Bb];
__device__ int g_off;

__global__ void prep_kernel(const unsigned char* __restrict__ mask, const int* offp) {
    int b = blockIdx.x;
    __shared__ int cnt;
    if (threadIdx.x == 0) cnt = 0;
    __syncthreads();
    bool w4 = (mask[1] == 0);
    int local = 0;
    for (int j = threadIdx.x; j < Ss; j += blockDim.x) {
        bool valid = w4 ? (((const unsigned int*)mask)[(size_t)b * Ss + j] != 0u)
                        : (mask[(size_t)b * Ss + j] != 0);
        local += valid ? 1 : 0;
    }
    atomicAdd(&cnt, local);
    __syncthreads();
    if (threadIdx.x == 0) {
        g_len[b] = cnt;
        if (b == 0) g_off = offp ? offp[0] : 0;
    }
}

__device__ __forceinline__ void split_pack(float x, float y, unsigned &hi, unsigned &lo) {
    __half2 hv = __floats2half2_rn(x, y);
    float2 hf = __half22float2(hv);
    __half2 lv = __floats2half2_rn(x - hf.x, y - hf.y);
    memcpy(&hi, &hv, 4);
    memcpy(&lo, &lv, 4);
}

__device__ __forceinline__ unsigned pack_h2(float x, float y) {
    __half2 hv = __floats2half2_rn(x, y);
    unsigned r; memcpy(&r, &hv, 4);
    return r;
}

__global__ void convert_kv(const float* __restrict__ K, const float* __restrict__ V) {
    size_t i = (size_t)blockIdx.x * blockDim.x + threadIdx.x;
    if (i >= TOT4) return;
    float4 k4 = ((const float4*)K)[i];
    uint2 hi, lo;
    split_pack(k4.x, k4.y, hi.x, lo.x);
    split_pack(k4.z, k4.w, hi.y, lo.y);
    ((uint2*)g_kh)[i] = hi; ((uint2*)g_kl)[i] = lo;
    float4 v4 = ((const float4*)V)[i];
    split_pack(v4.x, v4.y, hi.x, lo.x);
    split_pack(v4.z, v4.w, hi.y, lo.y);
    ((uint2*)g_vh)[i] = hi; ((uint2*)g_vl)[i] = lo;
}

#define LDSM4(r0,r1,r2,r3,addr) \
    asm volatile("ldmatrix.sync.aligned.m8n8.x4.shared.b16 {%0,%1,%2,%3}, [%4];\n" \
        : "=r"(r0),"=r"(r1),"=r"(r2),"=r"(r3) : "r"(addr))
#define LDSM4T(r0,r1,r2,r3,addr) \
    asm volatile("ldmatrix.sync.aligned.m8n8.x4.trans.shared.b16 {%0,%1,%2,%3}, [%4];\n" \
        : "=r"(r0),"=r"(r1),"=r"(r2),"=r"(r3) : "r"(addr))
#define MMA_F16(c,a,b0,b1) \
    asm volatile("mma.sync.aligned.m16n8k16.row.col.f32.f16.f16.f32 " \
        "{%0,%1,%2,%3}, {%4,%5,%6,%7}, {%8,%9}, {%0,%1,%2,%3};\n" \
        : "+f"(c[0]),"+f"(c[1]),"+f"(c[2]),"+f"(c[3]) \
        : "r"(a[0]),"r"(a[1]),"r"(a[2]),"r"(a[3]),"r"(b0),"r"(b1))
#define CPA16(dst, src) \
    asm volatile("cp.async.cg.shared.global [%0], [%1], 16;" :: "r"(dst), "l"(src) : "memory")
#define CPA_COMMIT() asm volatile("cp.async.commit_group;" ::: "memory")
#define CPA_WAIT0()  asm volatile("cp.async.wait_group 0;" ::: "memory")

// stage one 32-row K/V tile (4 planes) via cp.async; 128 threads
__device__ __forceinline__ void stage_tile(unsigned sb, unsigned bufE, size_t gbase,
                                           int tid) {
    const int c = tid & 15;
    const int r0 = tid >> 4;
    const unsigned dstb = sb + bufE * 2 + (unsigned)c * 16;
    const size_t srcb = gbase + (size_t)c * 8;
    #pragma unroll
    for (int j = 0; j < 4; j++) {
        const int r = r0 + 8 * j;
        const unsigned drow = (unsigned)r * (SK * 2);
        const size_t srow = srcb + (size_t)r * Dd;
        CPA16(dstb + KH_O * 2 + drow, g_kh + srow);
        CPA16(dstb + KL_O * 2 + drow, g_kl + srow);
        CPA16(dstb + VH_O * 2 + drow, g_vh + srow);
        CPA16(dstb + VL_O * 2 + drow, g_vl + srow);
    }
}

__global__ __launch_bounds__(NT, 2)
void attend_kernel(const float* __restrict__ Q, const float* __restrict__ Bias,
                   float* __restrict__ Out) {
    extern __shared__ unsigned short sm16[];

    const int tid = threadIdx.x;
    const int lane = tid & 31, w = tid >> 5;
    const int g = lane >> 2, t4 = lane & 3;
    const int lm = lane & 7, sel = lane >> 3;
    const int m0 = w * 16;

    const int bh = blockIdx.y;
    const int b = bh / Hh;
    const int h = bh - b * Hh;
    const int q0 = (gridDim.x - 1 - blockIdx.x) * BM;  // heavy CTAs first

    const int L = g_len[b];
    const int off = g_off;

    const float* qb = Q + ((size_t)bh * Ss + q0) * Dd;
    const float* bb = Bias + (size_t)h * Ss * Ss;
    float* ob = Out + ((size_t)bh * Ss + q0) * Dd;
    const size_t kvbase = (size_t)bh * Ss * Dd;

    // ---- stage Q (64 x 128) as fp16 hi only ----
    #pragma unroll 4
    for (int t = tid; t < BM * (Dd / 4); t += NT) {
        int r = t >> 5, c4 = t & 31;
        float4 v = ((const float4*)(qb + (size_t)r * Dd))[c4];
        int base = r * SQ + c4 * 4;
        *(unsigned*)&sm16[OFF_QH + base]     = pack_h2(v.x, v.y);
        *(unsigned*)&sm16[OFF_QH + base + 2] = pack_h2(v.z, v.w);
    }

    // fragment lane addressing
    const unsigned smemB = (unsigned)__cvta_generic_to_shared(sm16);
    const int rowA  = m0 + lm + (sel & 1) * 8;
    const int rowBK = lm + ((sel & 2) >> 1) * 8;
    const int rowBV = lm + (sel & 1) * 8;
    const unsigned selA16 = ((sel & 2) >> 1) * 16;
    const unsigned selB16 = (sel & 1) * 16;

    const unsigned aQH = smemB + (OFF_QH + rowA * SQ) * 2 + selA16;
    const unsigned laneKH = (unsigned)(KH_O + rowBK * SK) * 2 + selB16;
    const unsigned laneKL = (unsigned)(KL_O + rowBK * SK) * 2 + selB16;
    const unsigned laneVH = (unsigned)(VH_O + rowBV * SK) * 2 + selA16;
    const unsigned laneVL = (unsigned)(VL_O + rowBV * SK) * 2 + selA16;

    float o[16][4];
    #pragma unroll
    for (int nf = 0; nf < 16; nf++)
        #pragma unroll
        for (int c = 0; c < 4; c++) o[nf][c] = 0.f;
    float mrow0 = -1e30f, mrow1 = -1e30f, lrow0 = 0.f, lrow1 = 0.f;

    const int i0 = q0 + m0 + g;
    const int i1 = i0 + 8;

    int maxj = q0 + BM - 1 - off;
    if (maxj > L - 1) maxj = L - 1;
    const int ntiles = (maxj >= 0) ? (maxj / BN + 1) : 0;

    const float scale = 0.08838834764831845f;  // 128^-0.5

    // bias register double buffer: bC = tile t, bN = tile t+1
    float2 bC[8], bN[8];

    if (ntiles > 0) {
        stage_tile(smemB, BUF0, kvbase, tid);
        CPA_COMMIT();
        #pragma unroll
        for (int nf = 0; nf < 4; nf++) {
            const int j0 = nf * 8 + 2 * t4;
            bC[2 * nf]     = __ldg((const float2*)(bb + (size_t)i0 * Ss + j0));
            bC[2 * nf + 1] = __ldg((const float2*)(bb + (size_t)i1 * Ss + j0));
        }
    }

    for (int t = 0; t < ntiles; ++t) {
        const int n0 = t * BN;
        const bool have_next = (t + 1 < ntiles);
        CPA_WAIT0();
        __syncthreads();

        if (have_next) {
            stage_tile(smemB, BUF0 + (unsigned)((t + 1) & 1) * BUFSZ,
                       kvbase + (size_t)(n0 + BN) * Dd, tid);
            CPA_COMMIT();
            const int nn0 = n0 + BN;
            #pragma unroll
            for (int nf = 0; nf < 4; nf++) {
                const int j0 = nn0 + nf * 8 + 2 * t4;
                bN[2 * nf]     = __ldg((const float2*)(bb + (size_t)i0 * Ss + j0));
                bN[2 * nf + 1] = __ldg((const float2*)(bb + (size_t)i1 * Ss + j0));
            }
        }

        const unsigned bufB = smemB + (BUF0 + (unsigned)(t & 1) * BUFSZ) * 2;
        const unsigned bKH = bufB + laneKH;
        const unsigned bKL = bufB + laneKL;
        const unsigned bVH = bufB + laneVH;
        const unsigned bVL = bufB + laneVL;

        // ---- S = Q @ K^T (fp16 2-term: Qh*Kh + Qh*Kl) ----
        float acc[4][4];
        #pragma unroll
        for (int nf = 0; nf < 4; nf++)
            #pragma unroll
            for (int c = 0; c < 4; c++) acc[nf][c] = 0.f;

        #pragma unroll
        for (int kk = 0; kk < 8; kk++) {
            unsigned ah[4], kh4[2][4], kl4[2][4];
            LDSM4(ah[0], ah[1], ah[2], ah[3], aQH + kk * 32);
            #pragma unroll
            for (int nf2 = 0; nf2 < 2; nf2++) {
                const unsigned boff = nf2 * (16 * SK * 2) + kk * 32;
                LDSM4(kh4[nf2][0], kh4[nf2][1], kh4[nf2][2], kh4[nf2][3], bKH + boff);
                LDSM4(kl4[nf2][0], kl4[nf2][1], kl4[nf2][2], kl4[nf2][3], bKL + boff);
            }
            #pragma unroll
            for (int nf2 = 0; nf2 < 2; nf2++) {
                MMA_F16(acc[2 * nf2],     ah, kh4[nf2][0], kh4[nf2][1]);
                MMA_F16(acc[2 * nf2 + 1], ah, kh4[nf2][2], kh4[nf2][3]);
            }
            #pragma unroll
            for (int nf2 = 0; nf2 < 2; nf2++) {
                MMA_F16(acc[2 * nf2],     ah, kl4[nf2][0], kl4[nf2][1]);
                MMA_F16(acc[2 * nf2 + 1], ah, kl4[nf2][2], kl4[nf2][3]);
            }
        }

        // ---- scale + bias (prefetched) + mask ----
        const bool full = (n0 + BN - 1 <= q0 - off) && (n0 + BN <= L);
        #pragma unroll
        for (int nf = 0; nf < 4; nf++) {
            const int j0 = n0 + nf * 8 + 2 * t4;
            const float2 bi0 = bC[2 * nf];
            const float2 bi1 = bC[2 * nf + 1];
            if (full) {
                acc[nf][0] = acc[nf][0] * scale + bi0.x;
                acc[nf][1] = acc[nf][1] * scale + bi0.y;
                acc[nf][2] = acc[nf][2] * scale + bi1.x;
                acc[nf][3] = acc[nf][3] * scale + bi1.y;
            } else {
                acc[nf][0] = (j0     <= i0 - off && j0     < L) ? acc[nf][0] * scale + bi0.x : -1e30f;
                acc[nf][1] = (j0 + 1 <= i0 - off && j0 + 1 < L) ? acc[nf][1] * scale + bi0.y : -1e30f;
                acc[nf][2] = (j0     <= i1 - off && j0     < L) ? acc[nf][2] * scale + bi1.x : -1e30f;
                acc[nf][3] = (j0 + 1 <= i1 - off && j0 + 1 < L) ? acc[nf][3] * scale + bi1.y : -1e30f;
            }
        }

        // ---- online softmax; P packed (single fp16) into A-fragment registers ----
        float mx0 = acc[0][0], mx1 = acc[0][2];
        #pragma unroll
        for (int nf = 0; nf < 4; nf++) {
            mx0 = fmaxf(mx0, fmaxf(acc[nf][0], acc[nf][1]));
            mx1 = fmaxf(mx1, fmaxf(acc[nf][2], acc[nf][3]));
        }
        mx0 = fmaxf(mx0, __shfl_xor_sync(0xFFFFFFFFu, mx0, 1));
        mx0 = fmaxf(mx0, __shfl_xor_sync(0xFFFFFFFFu, mx0, 2));
        mx1 = fmaxf(mx1, __shfl_xor_sync(0xFFFFFFFFu, mx1, 1));
        mx1 = fmaxf(mx1, __shfl_xor_sync(0xFFFFFFFFu, mx1, 2));
        const float mn0 = fmaxf(mrow0, mx0);
        const float mn1 = fmaxf(mrow1, mx1);
        const float alpha0 = __expf(mrow0 - mn0);
        const float alpha1 = __expf(mrow1 - mn1);
        float sum0 = 0.f, sum1 = 0.f;

        unsigned ph01[4], ph23[4];
        #pragma unroll
        for (int nf = 0; nf < 4; nf++) {
            float p00 = __expf(acc[nf][0] - mn0);
            float p01 = __expf(acc[nf][1] - mn0);
            float p10 = __expf(acc[nf][2] - mn1);
            float p11 = __expf(acc[nf][3] - mn1);
            sum0 += p00 + p01;
            sum1 += p10 + p11;
            ph01[nf] = pack_h2(p00, p01);
            ph23[nf] = pack_h2(p10, p11);
        }
        sum0 += __shfl_xor_sync(0xFFFFFFFFu, sum0, 1);
        sum0 += __shfl_xor_sync(0xFFFFFFFFu, sum0, 2);
        sum1 += __shfl_xor_sync(0xFFFFFFFFu, sum1, 1);
        sum1 += __shfl_xor_sync(0xFFFFFFFFu, sum1, 2);
        lrow0 = lrow0 * alpha0 + sum0;
        lrow1 = lrow1 * alpha1 + sum1;
        mrow0 = mn0; mrow1 = mn1;

        if (alpha0 != 1.0f || alpha1 != 1.0f) {
            #pragma unroll
            for (int nf = 0; nf < 16; nf++) {
                o[nf][0] *= alpha0; o[nf][1] *= alpha0;
                o[nf][2] *= alpha1; o[nf][3] *= alpha1;
            }
        }

        // ---- O += P @ V (fp16 2-term: Ph*Vh + Ph*Vl) ----
        #pragma unroll
        for (int kk = 0; kk < 2; kk++) {
            unsigned ah[4];
            ah[0] = ph01[2 * kk];
            ah[1] = ph23[2 * kk];
            ah[2] = ph01[2 * kk + 1];
            ah[3] = ph23[2 * kk + 1];
            #pragma unroll
            for (int vh = 0; vh < 2; vh++) {
                unsigned bh4[4][4], bl4[4][4];
                #pragma unroll
                for (int qd = 0; qd < 4; qd++) {
                    const int nf2 = vh * 4 + qd;
                    const unsigned boff = kk * (16 * SK * 2) + nf2 * 32;
                    LDSM4T(bh4[qd][0], bh4[qd][1], bh4[qd][2], bh4[qd][3], bVH + boff);
                    LDSM4T(bl4[qd][0], bl4[qd][1], bl4[qd][2], bl4[qd][3], bVL + boff);
                }
                #pragma unroll
                for (int qd = 0; qd < 4; qd++) {
                    const int nf2 = vh * 4 + qd;
                    MMA_F16(o[2 * nf2],     ah, bh4[qd][0], bh4[qd][1]);
                    MMA_F16(o[2 * nf2 + 1], ah, bh4[qd][2], bh4[qd][3]);
                }
                #pragma unroll
                for (int qd = 0; qd < 4; qd++) {
                    const int nf2 = vh * 4 + qd;
                    MMA_F16(o[2 * nf2],     ah, bl4[qd][0], bl4[qd][1]);
                    MMA_F16(o[2 * nf2 + 1], ah, bl4[qd][2], bl4[qd][3]);
                }
            }
        }

        // rotate bias buffer
        if (have_next) {
            #pragma unroll
            for (int i = 0; i < 8; i++) bC[i] = bN[i];
        }
    }

    // ---- normalize + write ----
    const float inv0 = (lrow0 > 0.f) ? (1.f / lrow0) : 0.f;
    const float inv1 = (lrow1 > 0.f) ? (1.f / lrow1) : 0.f;
    float* o0 = ob + (size_t)(m0 + g) * Dd + 2 * t4;
    float* o1 = ob + (size_t)(m0 + g + 8) * Dd + 2 * t4;
    #pragma unroll
    for (int nf = 0; nf < 16; nf++) {
        float2 w0 = make_float2(o[nf][0] * inv0, o[nf][1] * inv0);
        float2 w1 = make_float2(o[nf][2] * inv1, o[nf][3] * inv1);
        *(float2*)&o0[nf * 8] = w0;
        *(float2*)&o1[nf * 8] = w1;
    }
}

extern "C" void kernel_launch(void* const* d_in, const int* in_sizes, int n_in,
                              void* d_out, int out_size) {
    const float* q = (const float*)d_in[0];
    const float* k = (const float*)d_in[1];
    const float* v = (const float*)d_in[2];
    const unsigned char* mask = (const unsigned char*)d_in[3];
    const float* bias = (const float*)d_in[4];
    const int* off = (n_in > 5) ? (const int*)d_in[5] : nullptr;
    float* out = (float*)d_out;

    cudaFuncSetAttribute(attend_kernel,
                         cudaFuncAttributeMaxDynamicSharedMemorySize, SMEM_BYTES);

    prep_kernel<<<Bb, 256>>>(mask, off);
    convert_kv<<<(int)(TOT4 / 256), 256>>>(k, v);
    dim3 grid(Ss / BM, Bb * Hh);
    attend_kernel<<<grid, NT, SMEM_BYTES>>>(q, bias, out);
}